// round 1
// baseline (speedup 1.0000x reference)
#include <cuda_runtime.h>
#include <math.h>

// Problem constants
#define CC    256          // channels
#define HH    256          // equirect height
#define WW    512          // equirect width
#define NPIX  (HH*WW)      // 131072 (= 1<<17)
#define FH    256          // cube face size

// Conv tiling
#define ICC   8            // input-channel chunk
#define OCT   64           // output channels per block
#define TY    8            // tile rows
#define TX    32           // tile cols
#define SIW   35           // smem input row stride (odd -> conflict-free)

// ---------------------------------------------------------------------------
// Device scratch (static — no allocations allowed)
// ---------------------------------------------------------------------------
__device__ float g_aux  [CC * NPIX];   // cube2equi result      (128 MB)
__device__ float g_Maux [CC * NPIX];   // relu(conv(aux))       (128 MB)
__device__ float g_Wt   [CC * 9 * CC]; // weights as [ic][tap][oc]
__device__ float g_sMain[4 * NPIX];    // per-ocgroup partial mask logits (main)
__device__ float g_sAux [4 * NPIX];    // per-ocgroup partial mask logits (aux)
__device__ float g_mask [NPIX];        // sigmoid(mask logit)
__device__ int   g_face [NPIX];
__device__ int   g_off  [NPIX * 4];
__device__ float g_gw   [NPIX * 4];

// ---------------------------------------------------------------------------
// 1) Per-pixel cube2equi geometry (face select + bilinear corners/weights)
// ---------------------------------------------------------------------------
__global__ void geo_kernel() {
    int p = blockIdx.x * blockDim.x + threadIdx.x;
    if (p >= NPIX) return;
    int oy = p / WW, ox = p % WW;

    const float PI = 3.14159265358979323846f;
    float theta = ((ox + 0.5f) / (float)WW) * (2.0f * PI) - PI;
    float phi   = 0.5f * PI - ((oy + 0.5f) / (float)HH) * PI;

    float st = sinf(theta), ct = cosf(theta);
    float sp = sinf(phi),   cp = cosf(phi);
    float dx = cp * st, dy = sp, dz = cp * ct;

    float ax = fabsf(dx), ay = fabsf(dy), az = fabsf(dz);
    float mx = fmaxf(fmaxf(ax, ay), az);
    float px = dx / mx, py = dy / mx, pz = dz / mx;

    bool cz = (az >= ax) && (az >= ay);
    bool cx = (!cz) && (ax >= ay);

    int face = cz ? (dz > 0.f ? 2 : 0)
             : cx ? (dx > 0.f ? 4 : 3)
                  : (dy > 0.f ? 5 : 1);

    float a  = cz ? (dz > 0.f ? px : -px)
             : cx ? (dx > 0.f ? -pz : pz)
                  : px;
    float bc = (cz || cx) ? -py : (dy > 0.f ? pz : -pz);

    float uu = fminf(fmaxf((a  + 1.0f) * 0.5f * (float)(FH - 1), 0.0f), (float)(FH - 1));
    float vv = fminf(fmaxf((bc + 1.0f) * 0.5f * (float)(FH - 1), 0.0f), (float)(FH - 1));

    int u0 = (int)floorf(uu), v0 = (int)floorf(vv);
    int u1 = min(u0 + 1, FH - 1), v1 = min(v0 + 1, FH - 1);
    float wu = uu - (float)u0, wv = vv - (float)v0;

    g_face[p] = face;
    g_off[p * 4 + 0] = v0 * FH + u0;
    g_off[p * 4 + 1] = v0 * FH + u1;
    g_off[p * 4 + 2] = v1 * FH + u0;
    g_off[p * 4 + 3] = v1 * FH + u1;
    g_gw [p * 4 + 0] = (1.f - wv) * (1.f - wu);
    g_gw [p * 4 + 1] = (1.f - wv) * wu;
    g_gw [p * 4 + 2] = wv * (1.f - wu);
    g_gw [p * 4 + 3] = wv * wu;
}

// ---------------------------------------------------------------------------
// 2) Build aux = cube2equi(cube) for all channels
// ---------------------------------------------------------------------------
__global__ void aux_kernel(const float* __restrict__ fb,
                           const float* __restrict__ fd,
                           const float* __restrict__ fu) {
    int idx = blockIdx.x * blockDim.x + threadIdx.x;
    if (idx >= CC * NPIX) return;
    int p = idx & (NPIX - 1);
    int c = idx >> 17;

    int f = g_face[p];
    const float* base = (f == 0) ? fb : (f == 1) ? fd : (f == 5) ? fu : nullptr;

    float v = 0.0f;
    if (base) {
        const float* bc = base + c * (FH * FH);
        v = g_gw[p*4+0] * bc[g_off[p*4+0]]
          + g_gw[p*4+1] * bc[g_off[p*4+1]]
          + g_gw[p*4+2] * bc[g_off[p*4+2]]
          + g_gw[p*4+3] * bc[g_off[p*4+3]];
    }
    g_aux[idx] = v;
}

// ---------------------------------------------------------------------------
// 3) Transpose Wf [oc][ic][3][3] -> g_Wt [ic][tap][oc] for coalesced LDS
// ---------------------------------------------------------------------------
__global__ void wt_kernel(const float* __restrict__ Wf) {
    int i = blockIdx.x * blockDim.x + threadIdx.x;
    if (i >= CC * CC * 9) return;
    int oc  = i / (CC * 9);
    int rem = i % (CC * 9);
    int ic  = rem / 9;
    int tap = rem % 9;
    g_Wt[(ic * 9 + tap) * CC + oc] = Wf[i];
}

// ---------------------------------------------------------------------------
// 4) Direct 3x3 conv + bias + ReLU, fused per-pixel Wm-weighted channel sum.
//    Block: 64 oc x (8x32) px. Thread: 16 oc x 4 px (64 fp32 accumulators).
// ---------------------------------------------------------------------------
__global__ __launch_bounds__(256, 2)
void conv_kernel(const float* __restrict__ in,    // [CC][HH][WW]
                 const float* __restrict__ bias,  // [CC]
                 const float* __restrict__ wm,    // [CC] (segment of Wm)
                 float* __restrict__ out,         // [CC][NPIX] or null
                 float* __restrict__ sPart)       // [4][NPIX]
{
    __shared__ float sIn[ICC][TY + 2][SIW];
    __shared__ float sW [ICC][9][OCT];
    __shared__ float sRed[256][4];

    const int t   = threadIdx.x;
    const int ocg = t >> 6;        // 0..3 -> 16 oc each
    const int tp  = t & 63;
    const int r   = tp >> 3;       // 0..7 tile row
    const int cg  = tp & 7;        // 0..7 -> cols cg*4..cg*4+3
    const int x0  = blockIdx.x * TX;
    const int y0  = blockIdx.y * TY;
    const int oc0 = blockIdx.z * OCT;

    float acc[16][4];
#pragma unroll
    for (int i = 0; i < 16; i++)
#pragma unroll
        for (int j = 0; j < 4; j++) acc[i][j] = 0.0f;

    for (int ic0 = 0; ic0 < CC; ic0 += ICC) {
        __syncthreads();
        // -- load input tile with halo (zero padding at image borders) --
        for (int i = t; i < ICC * (TY + 2) * (TX + 2); i += 256) {
            int ic  = i / ((TY + 2) * (TX + 2));
            int rem = i % ((TY + 2) * (TX + 2));
            int yy  = rem / (TX + 2);
            int xx  = rem % (TX + 2);
            int gy  = y0 + yy - 1;
            int gx  = x0 + xx - 1;
            float v = 0.0f;
            if (gy >= 0 && gy < HH && gx >= 0 && gx < WW)
                v = in[(ic0 + ic) * NPIX + gy * WW + gx];
            sIn[ic][yy][xx] = v;
        }
        // -- load weight slab [ICC][9][OCT] --
        for (int i = t; i < ICC * 9 * OCT; i += 256) {
            int ic  = i / (9 * OCT);
            int rem = i % (9 * OCT);
            int tap = rem / OCT;
            int oc  = rem % OCT;
            sW[ic][tap][oc] = g_Wt[((ic0 + ic) * 9 + tap) * CC + oc0 + oc];
        }
        __syncthreads();

#pragma unroll 2
        for (int ic = 0; ic < ICC; ic++) {
#pragma unroll
            for (int ky = 0; ky < 3; ky++) {
                float xv[6];
#pragma unroll
                for (int j = 0; j < 6; j++)
                    xv[j] = sIn[ic][r + ky][cg * 4 + j];
#pragma unroll
                for (int kx = 0; kx < 3; kx++) {
                    const float4* wp = (const float4*)&sW[ic][ky * 3 + kx][ocg * 16];
                    float4 w0 = wp[0], w1 = wp[1], w2 = wp[2], w3 = wp[3];
                    float ww[16] = { w0.x, w0.y, w0.z, w0.w,
                                     w1.x, w1.y, w1.z, w1.w,
                                     w2.x, w2.y, w2.z, w2.w,
                                     w3.x, w3.y, w3.z, w3.w };
#pragma unroll
                    for (int i = 0; i < 16; i++)
#pragma unroll
                        for (int j = 0; j < 4; j++)
                            acc[i][j] = fmaf(ww[i], xv[kx + j], acc[i][j]);
                }
            }
        }
    }

    // -- epilogue: bias + ReLU, optional store, Wm-weighted partial sum --
    const int pbase = (y0 + r) * WW + x0 + cg * 4;
    float part[4] = {0.f, 0.f, 0.f, 0.f};
#pragma unroll
    for (int i = 0; i < 16; i++) {
        int oc    = oc0 + ocg * 16 + i;
        float bv  = bias[oc];
        float wmv = wm[oc];
#pragma unroll
        for (int j = 0; j < 4; j++) {
            float v = acc[i][j] + bv;
            v = v > 0.0f ? v : 0.0f;
            if (out) out[oc * NPIX + pbase + j] = v;
            part[j] = fmaf(wmv, v, part[j]);
        }
    }
    __syncthreads();                 // sIn/sW reads done; safe to reuse barrier
#pragma unroll
    for (int j = 0; j < 4; j++) sRed[t][j] = part[j];
    __syncthreads();
    if (ocg == 0) {                  // deterministic in-block reduction (no atomics)
#pragma unroll
        for (int j = 0; j < 4; j++) {
            float s = sRed[t][j] + sRed[t + 64][j] + sRed[t + 128][j] + sRed[t + 192][j];
            sPart[blockIdx.z * NPIX + pbase + j] = s;
        }
    }
}

// ---------------------------------------------------------------------------
// 5) mask = sigmoid(bm + sum of partials)
// ---------------------------------------------------------------------------
__global__ void mask_kernel(const float* __restrict__ bm) {
    int p = blockIdx.x * blockDim.x + threadIdx.x;
    if (p >= NPIX) return;
    float s = bm[0];
#pragma unroll
    for (int z = 0; z < 4; z++)
        s += g_sMain[z * NPIX + p] + g_sAux[z * NPIX + p];
    g_mask[p] = 1.0f / (1.0f + expf(-s));
}

// ---------------------------------------------------------------------------
// 6) out = m + mask * M_aux   (float4 vectorized)
// ---------------------------------------------------------------------------
__global__ void final_kernel(const float* __restrict__ m, float* __restrict__ out) {
    int i4 = blockIdx.x * blockDim.x + threadIdx.x;   // index of float4
    if (i4 >= (CC * NPIX) / 4) return;
    int idx = i4 * 4;
    int p   = idx & (NPIX - 1);
    const float4 mv = ((const float4*)m)[i4];
    const float4 av = ((const float4*)g_Maux)[i4];
    const float4 kv = *(const float4*)&g_mask[p];     // p is 4-aligned
    float4 o;
    o.x = fmaf(kv.x, av.x, mv.x);
    o.y = fmaf(kv.y, av.y, mv.y);
    o.z = fmaf(kv.z, av.z, mv.z);
    o.w = fmaf(kv.w, av.w, mv.w);
    ((float4*)out)[i4] = o;
}

// ---------------------------------------------------------------------------
// Launch
// ---------------------------------------------------------------------------
extern "C" void kernel_launch(void* const* d_in, const int* in_sizes, int n_in,
                              void* d_out, int out_size) {
    const float* m  = (const float*)d_in[0];
    const float* fb = (const float*)d_in[1];
    const float* fu = (const float*)d_in[2];
    const float* fd = (const float*)d_in[3];
    const float* Wf = (const float*)d_in[4];
    const float* bf = (const float*)d_in[5];
    const float* Wm = (const float*)d_in[6];
    const float* bm = (const float*)d_in[7];
    float* out = (float*)d_out;

    float* gAux   = nullptr; cudaGetSymbolAddress((void**)&gAux,   g_aux);
    float* gMaux  = nullptr; cudaGetSymbolAddress((void**)&gMaux,  g_Maux);
    float* gSMain = nullptr; cudaGetSymbolAddress((void**)&gSMain, g_sMain);
    float* gSAux  = nullptr; cudaGetSymbolAddress((void**)&gSAux,  g_sAux);

    // 1) geometry
    geo_kernel<<<(NPIX + 255) / 256, 256>>>();
    // 2) weight transpose
    wt_kernel<<<(CC * CC * 9 + 255) / 256, 256>>>(Wf);
    // 3) aux construction
    aux_kernel<<<(CC * NPIX + 255) / 256, 256>>>(fb, fd, fu);
    // 4) two convs (main conv: no output tensor, only mask partials)
    dim3 cgrid(WW / TX, HH / TY, CC / OCT);   // 16 x 32 x 4
    conv_kernel<<<cgrid, 256>>>(m,    bf, Wm,       nullptr, gSMain);
    conv_kernel<<<cgrid, 256>>>(gAux, bf, Wm + CC,  gMaux,   gSAux);
    // 5) mask
    mask_kernel<<<(NPIX + 255) / 256, 256>>>(bm);
    // 6) residual gate
    final_kernel<<<((CC * NPIX) / 4 + 255) / 256, 256>>>(m, out);
}

// round 2
// speedup vs baseline: 1.0012x; 1.0012x over previous
#include <cuda_runtime.h>
#include <math.h>

// Problem constants
#define CC    256          // channels
#define HH    256          // equirect height
#define WW    512          // equirect width
#define NPIX  (HH*WW)      // 131072 (= 1<<17)
#define FH    256          // cube face size

// Conv tiling
#define ICC   8            // input-channel chunk
#define OCT   64           // output channels per block
#define TY    8            // tile rows
#define TX    32           // tile cols
#define SIW   35           // smem input row stride (odd -> conflict-free)

// ---------------------------------------------------------------------------
// Device scratch (static — no allocations allowed)
// ---------------------------------------------------------------------------
__device__ float g_aux  [CC * NPIX];   // cube2equi result      (128 MB)
__device__ float g_Maux [CC * NPIX];   // relu(conv(aux))       (128 MB)
__device__ float g_Wt   [CC * 9 * CC]; // weights as [ic][tap][oc]
__device__ float g_sMain[4 * NPIX];    // per-ocgroup partial mask logits (main)
__device__ float g_sAux [4 * NPIX];    // per-ocgroup partial mask logits (aux)
__device__ float g_mask [NPIX];        // sigmoid(mask logit)
__device__ int   g_face [NPIX];
__device__ int   g_off  [NPIX * 4];
__device__ float g_gw   [NPIX * 4];

// ---------------------------------------------------------------------------
// 1) Per-pixel cube2equi geometry (face select + bilinear corners/weights)
// ---------------------------------------------------------------------------
__global__ void geo_kernel() {
    int p = blockIdx.x * blockDim.x + threadIdx.x;
    if (p >= NPIX) return;
    int oy = p / WW, ox = p % WW;

    const float PI = 3.14159265358979323846f;
    float theta = ((ox + 0.5f) / (float)WW) * (2.0f * PI) - PI;
    float phi   = 0.5f * PI - ((oy + 0.5f) / (float)HH) * PI;

    float st = sinf(theta), ct = cosf(theta);
    float sp = sinf(phi),   cp = cosf(phi);
    float dx = cp * st, dy = sp, dz = cp * ct;

    float ax = fabsf(dx), ay = fabsf(dy), az = fabsf(dz);
    float mx = fmaxf(fmaxf(ax, ay), az);
    float px = dx / mx, py = dy / mx, pz = dz / mx;

    bool cz = (az >= ax) && (az >= ay);
    bool cx = (!cz) && (ax >= ay);

    int face = cz ? (dz > 0.f ? 2 : 0)
             : cx ? (dx > 0.f ? 4 : 3)
                  : (dy > 0.f ? 5 : 1);

    float a  = cz ? (dz > 0.f ? px : -px)
             : cx ? (dx > 0.f ? -pz : pz)
                  : px;
    float bc = (cz || cx) ? -py : (dy > 0.f ? pz : -pz);

    float uu = fminf(fmaxf((a  + 1.0f) * 0.5f * (float)(FH - 1), 0.0f), (float)(FH - 1));
    float vv = fminf(fmaxf((bc + 1.0f) * 0.5f * (float)(FH - 1), 0.0f), (float)(FH - 1));

    int u0 = (int)floorf(uu), v0 = (int)floorf(vv);
    int u1 = min(u0 + 1, FH - 1), v1 = min(v0 + 1, FH - 1);
    float wu = uu - (float)u0, wv = vv - (float)v0;

    g_face[p] = face;
    g_off[p * 4 + 0] = v0 * FH + u0;
    g_off[p * 4 + 1] = v0 * FH + u1;
    g_off[p * 4 + 2] = v1 * FH + u0;
    g_off[p * 4 + 3] = v1 * FH + u1;
    g_gw [p * 4 + 0] = (1.f - wv) * (1.f - wu);
    g_gw [p * 4 + 1] = (1.f - wv) * wu;
    g_gw [p * 4 + 2] = wv * (1.f - wu);
    g_gw [p * 4 + 3] = wv * wu;
}

// ---------------------------------------------------------------------------
// 2) Build aux = cube2equi(cube) for all channels
// ---------------------------------------------------------------------------
__global__ void aux_kernel(const float* __restrict__ fb,
                           const float* __restrict__ fd,
                           const float* __restrict__ fu) {
    int idx = blockIdx.x * blockDim.x + threadIdx.x;
    if (idx >= CC * NPIX) return;
    int p = idx & (NPIX - 1);
    int c = idx >> 17;

    int f = g_face[p];
    const float* base = (f == 0) ? fb : (f == 1) ? fd : (f == 5) ? fu : nullptr;

    float v = 0.0f;
    if (base) {
        const float* bc = base + c * (FH * FH);
        v = g_gw[p*4+0] * bc[g_off[p*4+0]]
          + g_gw[p*4+1] * bc[g_off[p*4+1]]
          + g_gw[p*4+2] * bc[g_off[p*4+2]]
          + g_gw[p*4+3] * bc[g_off[p*4+3]];
    }
    g_aux[idx] = v;
}

// ---------------------------------------------------------------------------
// 3) Transpose Wf [oc][ic][3][3] -> g_Wt [ic][tap][oc] for coalesced LDS
// ---------------------------------------------------------------------------
__global__ void wt_kernel(const float* __restrict__ Wf) {
    int i = blockIdx.x * blockDim.x + threadIdx.x;
    if (i >= CC * CC * 9) return;
    int oc  = i / (CC * 9);
    int rem = i % (CC * 9);
    int ic  = rem / 9;
    int tap = rem % 9;
    g_Wt[(ic * 9 + tap) * CC + oc] = Wf[i];
}

// ---------------------------------------------------------------------------
// 4) Direct 3x3 conv + bias + ReLU, fused per-pixel Wm-weighted channel sum.
//    Block: 64 oc x (8x32) px. Thread: 16 oc x 4 px (64 fp32 accumulators).
// ---------------------------------------------------------------------------
__global__ __launch_bounds__(256, 2)
void conv_kernel(const float* __restrict__ in,    // [CC][HH][WW]
                 const float* __restrict__ bias,  // [CC]
                 const float* __restrict__ wm,    // [CC] (segment of Wm)
                 float* __restrict__ out,         // [CC][NPIX] or null
                 float* __restrict__ sPart)       // [4][NPIX]
{
    __shared__ float sIn[ICC][TY + 2][SIW];
    __shared__ float sW [ICC][9][OCT];
    __shared__ float sRed[256][4];

    const int t   = threadIdx.x;
    const int ocg = t >> 6;        // 0..3 -> 16 oc each
    const int tp  = t & 63;
    const int r   = tp >> 3;       // 0..7 tile row
    const int cg  = tp & 7;        // 0..7 -> cols cg*4..cg*4+3
    const int x0  = blockIdx.x * TX;
    const int y0  = blockIdx.y * TY;
    const int oc0 = blockIdx.z * OCT;

    float acc[16][4];
#pragma unroll
    for (int i = 0; i < 16; i++)
#pragma unroll
        for (int j = 0; j < 4; j++) acc[i][j] = 0.0f;

    for (int ic0 = 0; ic0 < CC; ic0 += ICC) {
        __syncthreads();
        // -- load input tile with halo (zero padding at image borders) --
        for (int i = t; i < ICC * (TY + 2) * (TX + 2); i += 256) {
            int ic  = i / ((TY + 2) * (TX + 2));
            int rem = i % ((TY + 2) * (TX + 2));
            int yy  = rem / (TX + 2);
            int xx  = rem % (TX + 2);
            int gy  = y0 + yy - 1;
            int gx  = x0 + xx - 1;
            float v = 0.0f;
            if (gy >= 0 && gy < HH && gx >= 0 && gx < WW)
                v = in[(ic0 + ic) * NPIX + gy * WW + gx];
            sIn[ic][yy][xx] = v;
        }
        // -- load weight slab [ICC][9][OCT] --
        for (int i = t; i < ICC * 9 * OCT; i += 256) {
            int ic  = i / (9 * OCT);
            int rem = i % (9 * OCT);
            int tap = rem / OCT;
            int oc  = rem % OCT;
            sW[ic][tap][oc] = g_Wt[((ic0 + ic) * 9 + tap) * CC + oc0 + oc];
        }
        __syncthreads();

#pragma unroll 2
        for (int ic = 0; ic < ICC; ic++) {
#pragma unroll
            for (int ky = 0; ky < 3; ky++) {
                float xv[6];
#pragma unroll
                for (int j = 0; j < 6; j++)
                    xv[j] = sIn[ic][r + ky][cg * 4 + j];
#pragma unroll
                for (int kx = 0; kx < 3; kx++) {
                    const float4* wp = (const float4*)&sW[ic][ky * 3 + kx][ocg * 16];
                    float4 w0 = wp[0], w1 = wp[1], w2 = wp[2], w3 = wp[3];
                    float ww[16] = { w0.x, w0.y, w0.z, w0.w,
                                     w1.x, w1.y, w1.z, w1.w,
                                     w2.x, w2.y, w2.z, w2.w,
                                     w3.x, w3.y, w3.z, w3.w };
#pragma unroll
                    for (int i = 0; i < 16; i++)
#pragma unroll
                        for (int j = 0; j < 4; j++)
                            acc[i][j] = fmaf(ww[i], xv[kx + j], acc[i][j]);
                }
            }
        }
    }

    // -- epilogue: bias + ReLU, optional store, Wm-weighted partial sum --
    const int pbase = (y0 + r) * WW + x0 + cg * 4;
    float part[4] = {0.f, 0.f, 0.f, 0.f};
#pragma unroll
    for (int i = 0; i < 16; i++) {
        int oc    = oc0 + ocg * 16 + i;
        float bv  = bias[oc];
        float wmv = wm[oc];
#pragma unroll
        for (int j = 0; j < 4; j++) {
            float v = acc[i][j] + bv;
            v = v > 0.0f ? v : 0.0f;
            if (out) out[oc * NPIX + pbase + j] = v;
            part[j] = fmaf(wmv, v, part[j]);
        }
    }
    __syncthreads();                 // sIn/sW reads done; safe to reuse barrier
#pragma unroll
    for (int j = 0; j < 4; j++) sRed[t][j] = part[j];
    __syncthreads();
    if (ocg == 0) {                  // deterministic in-block reduction (no atomics)
#pragma unroll
        for (int j = 0; j < 4; j++) {
            float s = sRed[t][j] + sRed[t + 64][j] + sRed[t + 128][j] + sRed[t + 192][j];
            sPart[blockIdx.z * NPIX + pbase + j] = s;
        }
    }
}

// ---------------------------------------------------------------------------
// 5) mask = sigmoid(bm + sum of partials)
// ---------------------------------------------------------------------------
__global__ void mask_kernel(const float* __restrict__ bm) {
    int p = blockIdx.x * blockDim.x + threadIdx.x;
    if (p >= NPIX) return;
    float s = bm[0];
#pragma unroll
    for (int z = 0; z < 4; z++)
        s += g_sMain[z * NPIX + p] + g_sAux[z * NPIX + p];
    g_mask[p] = 1.0f / (1.0f + expf(-s));
}

// ---------------------------------------------------------------------------
// 6) out = m + mask * M_aux   (float4 vectorized)
// ---------------------------------------------------------------------------
__global__ void final_kernel(const float* __restrict__ m, float* __restrict__ out) {
    int i4 = blockIdx.x * blockDim.x + threadIdx.x;   // index of float4
    if (i4 >= (CC * NPIX) / 4) return;
    int idx = i4 * 4;
    int p   = idx & (NPIX - 1);
    const float4 mv = ((const float4*)m)[i4];
    const float4 av = ((const float4*)g_Maux)[i4];
    const float4 kv = *(const float4*)&g_mask[p];     // p is 4-aligned
    float4 o;
    o.x = fmaf(kv.x, av.x, mv.x);
    o.y = fmaf(kv.y, av.y, mv.y);
    o.z = fmaf(kv.z, av.z, mv.z);
    o.w = fmaf(kv.w, av.w, mv.w);
    ((float4*)out)[i4] = o;
}

// ---------------------------------------------------------------------------
// Launch
// ---------------------------------------------------------------------------
extern "C" void kernel_launch(void* const* d_in, const int* in_sizes, int n_in,
                              void* d_out, int out_size) {
    const float* m  = (const float*)d_in[0];
    const float* fb = (const float*)d_in[1];
    const float* fu = (const float*)d_in[2];
    const float* fd = (const float*)d_in[3];
    const float* Wf = (const float*)d_in[4];
    const float* bf = (const float*)d_in[5];
    const float* Wm = (const float*)d_in[6];
    const float* bm = (const float*)d_in[7];
    float* out = (float*)d_out;

    float* gAux   = nullptr; cudaGetSymbolAddress((void**)&gAux,   g_aux);
    float* gMaux  = nullptr; cudaGetSymbolAddress((void**)&gMaux,  g_Maux);
    float* gSMain = nullptr; cudaGetSymbolAddress((void**)&gSMain, g_sMain);
    float* gSAux  = nullptr; cudaGetSymbolAddress((void**)&gSAux,  g_sAux);

    // 1) geometry
    geo_kernel<<<(NPIX + 255) / 256, 256>>>();
    // 2) weight transpose
    wt_kernel<<<(CC * CC * 9 + 255) / 256, 256>>>(Wf);
    // 3) aux construction
    aux_kernel<<<(CC * NPIX + 255) / 256, 256>>>(fb, fd, fu);
    // 4) two convs (main conv: no output tensor, only mask partials)
    dim3 cgrid(WW / TX, HH / TY, CC / OCT);   // 16 x 32 x 4
    conv_kernel<<<cgrid, 256>>>(m,    bf, Wm,       nullptr, gSMain);
    conv_kernel<<<cgrid, 256>>>(gAux, bf, Wm + CC,  gMaux,   gSAux);
    // 5) mask
    mask_kernel<<<(NPIX + 255) / 256, 256>>>(bm);
    // 6) residual gate
    final_kernel<<<((CC * NPIX) / 4 + 255) / 256, 256>>>(m, out);
}

// round 4
// speedup vs baseline: 3.3331x; 3.3292x over previous
#include <cuda_runtime.h>
#include <stdint.h>
#include <math.h>

#define CC    256
#define HH    256
#define WW    512
#define NPIX  (HH*WW)      // 131072
#define FH    256

// ---------------------------------------------------------------------------
// Device scratch (static — no allocations allowed)
// ---------------------------------------------------------------------------
__device__ float g_aux [(size_t)CC * NPIX];
__device__ float g_Maux[(size_t)CC * NPIX];
__device__ float g_Wb  [2 * 72 * 2048 * 2];   // frag-ordered tf32 weights (2.25MB)
__device__ float g_logitM[2 * NPIX];
__device__ float g_logitA[2 * NPIX];
__device__ float g_mask [NPIX];
__device__ int   g_face [NPIX];
__device__ int   g_off  [NPIX * 4];
__device__ float g_gw   [NPIX * 4];

// ---------------------------------------------------------------------------
// helpers
// ---------------------------------------------------------------------------
__device__ __forceinline__ uint32_t smem_u32(const void* p) {
    uint32_t a;
    asm("{ .reg .u64 t; cvta.to.shared.u64 t, %1; cvt.u32.u64 %0, t; }" : "=r"(a) : "l"(p));
    return a;
}
__device__ __forceinline__ uint32_t cvt_tf32(float f) {
    uint32_t u; asm("cvt.rna.tf32.f32 %0, %1;" : "=r"(u) : "f"(f)); return u;
}
__device__ __forceinline__ void sts128(uint32_t a, uint32_t x, uint32_t y, uint32_t z, uint32_t w) {
    asm volatile("st.shared.v4.b32 [%0], {%1,%2,%3,%4};" :: "r"(a), "r"(x), "r"(y), "r"(z), "r"(w) : "memory");
}
__device__ __forceinline__ void sts64(uint32_t a, uint32_t x, uint32_t y) {
    asm volatile("st.shared.v2.b32 [%0], {%1,%2};" :: "r"(a), "r"(x), "r"(y) : "memory");
}
__device__ __forceinline__ void lds128(uint32_t a, uint32_t* r) {
    asm volatile("ld.shared.v4.b32 {%0,%1,%2,%3}, [%4];"
                 : "=r"(r[0]), "=r"(r[1]), "=r"(r[2]), "=r"(r[3]) : "r"(a));
}
__device__ __forceinline__ void lds64(uint32_t a, uint32_t* r) {
    asm volatile("ld.shared.v2.b32 {%0,%1}, [%2];" : "=r"(r[0]), "=r"(r[1]) : "r"(a));
}
__device__ __forceinline__ void mma_tf32(float* d, const uint32_t* a, const uint32_t* b) {
    asm volatile(
        "mma.sync.aligned.m16n8k8.row.col.f32.tf32.tf32.f32 "
        "{%0,%1,%2,%3}, {%4,%5,%6,%7}, {%8,%9}, {%0,%1,%2,%3};"
        : "+f"(d[0]), "+f"(d[1]), "+f"(d[2]), "+f"(d[3])
        : "r"(a[0]), "r"(a[1]), "r"(a[2]), "r"(a[3]), "r"(b[0]), "r"(b[1]));
}

// ---------------------------------------------------------------------------
// 1) per-pixel cube2equi geometry
// ---------------------------------------------------------------------------
__global__ void geo_kernel() {
    int p = blockIdx.x * blockDim.x + threadIdx.x;
    if (p >= NPIX) return;
    int oy = p / WW, ox = p % WW;
    const float PI = 3.14159265358979323846f;
    float theta = ((ox + 0.5f) / (float)WW) * (2.0f * PI) - PI;
    float phi   = 0.5f * PI - ((oy + 0.5f) / (float)HH) * PI;
    float st = sinf(theta), ct = cosf(theta);
    float sp = sinf(phi),   cp = cosf(phi);
    float dx = cp * st, dy = sp, dz = cp * ct;
    float ax = fabsf(dx), ay = fabsf(dy), az = fabsf(dz);
    float mx = fmaxf(fmaxf(ax, ay), az);
    float px = dx / mx, py = dy / mx, pz = dz / mx;
    bool cz = (az >= ax) && (az >= ay);
    bool cx = (!cz) && (ax >= ay);
    int face = cz ? (dz > 0.f ? 2 : 0) : cx ? (dx > 0.f ? 4 : 3) : (dy > 0.f ? 5 : 1);
    float a  = cz ? (dz > 0.f ? px : -px) : cx ? (dx > 0.f ? -pz : pz) : px;
    float bc = (cz || cx) ? -py : (dy > 0.f ? pz : -pz);
    float uu = fminf(fmaxf((a  + 1.0f) * 0.5f * (float)(FH - 1), 0.0f), (float)(FH - 1));
    float vv = fminf(fmaxf((bc + 1.0f) * 0.5f * (float)(FH - 1), 0.0f), (float)(FH - 1));
    int u0 = (int)floorf(uu), v0 = (int)floorf(vv);
    int u1 = min(u0 + 1, FH - 1), v1 = min(v0 + 1, FH - 1);
    float wu = uu - (float)u0, wv = vv - (float)v0;
    g_face[p] = face;
    g_off[p*4+0] = v0 * FH + u0; g_off[p*4+1] = v0 * FH + u1;
    g_off[p*4+2] = v1 * FH + u0; g_off[p*4+3] = v1 * FH + u1;
    g_gw [p*4+0] = (1.f-wv)*(1.f-wu); g_gw[p*4+1] = (1.f-wv)*wu;
    g_gw [p*4+2] = wv*(1.f-wu);       g_gw[p*4+3] = wv*wu;
}

// ---------------------------------------------------------------------------
// 2) aux = cube2equi(cube)
// ---------------------------------------------------------------------------
__global__ void aux_kernel(const float* __restrict__ fb, const float* __restrict__ fd,
                           const float* __restrict__ fu) {
    int idx = blockIdx.x * blockDim.x + threadIdx.x;
    if (idx >= CC * NPIX) return;
    int p = idx & (NPIX - 1);
    int c = idx >> 17;
    int f = g_face[p];
    const float* base = (f == 0) ? fb : (f == 1) ? fd : (f == 5) ? fu : nullptr;
    float v = 0.0f;
    if (base) {
        const float* bc = base + (size_t)c * (FH * FH);
        v = g_gw[p*4+0]*bc[g_off[p*4+0]] + g_gw[p*4+1]*bc[g_off[p*4+1]]
          + g_gw[p*4+2]*bc[g_off[p*4+2]] + g_gw[p*4+3]*bc[g_off[p*4+3]];
    }
    g_aux[idx] = v;
}

// ---------------------------------------------------------------------------
// 3) weights -> fragment-ordered tf32: g_Wb[half][q=72][kstep=4][ntile=16][lane=32][2]
//    q = icc*9 + tap; frag: b0 -> ic=lane&3, b1 -> ic=(lane&3)+4; n = lane>>2
// ---------------------------------------------------------------------------
__global__ void wtb_kernel(const float* __restrict__ Wf) {
    int idx = blockIdx.x * blockDim.x + threadIdx.x;   // one float2 per thread
    if (idx >= 2 * 72 * 2048) return;
    int lane  = idx & 31;
    int ntile = (idx >> 5) & 15;
    int kstep = (idx >> 9) & 3;
    int qq    = idx >> 11;          // 0..143
    int q     = qq % 72;
    int half  = qq / 72;
    int icc = q / 9, tap = q % 9;
    int oc  = half * 128 + ntile * 8 + (lane >> 2);
    int ic0 = icc * 32 + kstep * 8 + (lane & 3);
    float b0 = Wf[(oc * CC + ic0) * 9 + tap];
    float b1 = Wf[(oc * CC + ic0 + 4) * 9 + tap];
    g_Wb[idx * 2 + 0] = __uint_as_float(cvt_tf32(b0));
    g_Wb[idx * 2 + 1] = __uint_as_float(cvt_tf32(b1));
}

// ---------------------------------------------------------------------------
// 4) tf32 mma.sync conv: CTA 128px x 128oc, 8 warps (2M x 4N), double buffer.
//    SMEM layout (bytes): A stages @0,16384; B stages @32768,49152;
//    bias @65536; wm @66048; sRed @66560 (4x128 floats)
// ---------------------------------------------------------------------------
#define SM_A0    0u
#define SM_B0    32768u
#define SM_BIAS  65536u
#define SM_WM    66048u
#define SM_RED   66560u
#define SMEM_SZ  68608

__global__ __launch_bounds__(256, 2)
void conv_mma(const float* __restrict__ in, const float* __restrict__ bias,
              const float* __restrict__ wm, float* __restrict__ outp,
              float* __restrict__ logit)
{
    extern __shared__ char smem[];
    const uint32_t sb = smem_u32(smem);

    const int t    = threadIdx.x;
    const int w    = t >> 5;
    const int lane = t & 31;
    const int mw   = w >> 2;        // 0..1
    const int nw   = w & 3;         // 0..3

    const int px0 = blockIdx.x * 128;
    const int y   = px0 >> 9;
    const int x0  = px0 & 511;
    const int ocb = blockIdx.y * 128;

    if (t < 128) {
        ((float*)(smem + SM_BIAS))[t] = bias[ocb + t];
        ((float*)(smem + SM_WM))[t]   = wm[ocb + t];
    }

    // per-thread producer slot constants
    // A slots: slot = t + i*256, i=0..3 ; slot = mtile<<7 | kstep<<5 | lane
    // values: a0=(m,k) a1=(m+8,k) a2=(m,k+4) a3=(m+8,k+4); m=mtile*16+(lane>>2), k=kstep*8+(lane&3)
    uint32_t aS[4][4];
    float2   bS[8];
    const float2* wbBase = (const float2*)g_Wb + (size_t)blockIdx.y * 72 * 2048;

    float acc[4][4][4];
#pragma unroll
    for (int i = 0; i < 4; i++)
#pragma unroll
        for (int j = 0; j < 4; j++)
#pragma unroll
            for (int k = 0; k < 4; k++) acc[i][j][k] = 0.0f;

    // ---- producer reg load for chunk q ----
    auto load_regs = [&](int q) {
        const int icc = q / 9, tap = q % 9;
        const int ky = tap / 3, kx = tap % 3;
        const int ic0 = icc * 32;
        const int sy = y + ky - 1;
        const bool yok = (sy >= 0) && (sy < HH);
#pragma unroll
        for (int i = 0; i < 4; i++) {
            const int slot  = t + i * 256;
            const int mtile = slot >> 7;
            const int kstep = (slot >> 5) & 3;
            const int ln    = slot & 31;
            const int m     = mtile * 16 + (ln >> 2);
            const int k     = kstep * 8 + (ln & 3);
            const int sxa   = x0 + m + kx - 1;
            const int sxb   = sxa + 8;
            const bool oka  = yok && (sxa >= 0) && (sxa < WW);
            const bool okb  = yok && (sxb >= 0) && (sxb < WW);
            const float* p0 = in + (size_t)(ic0 + k) * NPIX + sy * WW;
            const float* p1 = p0 + (size_t)4 * NPIX;
            float v0 = oka ? __ldg(p0 + sxa) : 0.0f;
            float v1 = okb ? __ldg(p0 + sxb) : 0.0f;
            float v2 = oka ? __ldg(p1 + sxa) : 0.0f;
            float v3 = okb ? __ldg(p1 + sxb) : 0.0f;
            aS[i][0] = cvt_tf32(v0); aS[i][1] = cvt_tf32(v1);
            aS[i][2] = cvt_tf32(v2); aS[i][3] = cvt_tf32(v3);
        }
        const float2* wb = wbBase + (size_t)q * 2048;
#pragma unroll
        for (int i = 0; i < 8; i++) bS[i] = __ldg(wb + t + i * 256);
    };
    auto store_stage = [&](int st) {
        const uint32_t ab = sb + SM_A0 + (uint32_t)st * 16384u;
        const uint32_t bb = sb + SM_B0 + (uint32_t)st * 16384u;
#pragma unroll
        for (int i = 0; i < 4; i++)
            sts128(ab + (uint32_t)(t + i * 256) * 16u, aS[i][0], aS[i][1], aS[i][2], aS[i][3]);
#pragma unroll
        for (int i = 0; i < 8; i++)
            sts64(bb + (uint32_t)(t + i * 256) * 8u,
                  __float_as_uint(bS[i].x), __float_as_uint(bS[i].y));
    };

    load_regs(0);
    store_stage(0);
    __syncthreads();

#pragma unroll 1
    for (int q = 0; q < 72; q++) {
        const int st = q & 1;
        if (q < 71) load_regs(q + 1);

        const uint32_t ab = sb + SM_A0 + (uint32_t)st * 16384u;
        const uint32_t bb = sb + SM_B0 + (uint32_t)st * 16384u;
#pragma unroll
        for (int ks = 0; ks < 4; ks++) {
            uint32_t af[4][4], bf[4][2];
#pragma unroll
            for (int mt = 0; mt < 4; mt++) {
                const int mtile = mw * 4 + mt;
                lds128(ab + (uint32_t)(((mtile * 4 + ks) * 32 + lane) * 16), af[mt]);
            }
#pragma unroll
            for (int nt = 0; nt < 4; nt++) {
                const int ntile = nw * 4 + nt;
                lds64(bb + (uint32_t)(((ks * 16 + ntile) * 32 + lane) * 8), bf[nt]);
            }
#pragma unroll
            for (int mt = 0; mt < 4; mt++)
#pragma unroll
                for (int nt = 0; nt < 4; nt++)
                    mma_tf32(acc[mt][nt], af[mt], bf[nt]);
        }

        if (q < 71) store_stage(st ^ 1);
        __syncthreads();
    }

    // ---- epilogue: bias+ReLU, optional store, Wm-dot -> per-pixel partial ----
    const float* sBias = (const float*)(smem + SM_BIAS);
    const float* sWm   = (const float*)(smem + SM_WM);
    float* sRed        = (float*)(smem + SM_RED);

    float lp[4][2];
#pragma unroll
    for (int mt = 0; mt < 4; mt++) { lp[mt][0] = 0.f; lp[mt][1] = 0.f; }

#pragma unroll
    for (int mt = 0; mt < 4; mt++) {
        const int pxa = px0 + mw * 64 + mt * 16 + (lane >> 2);
        const int pxb = pxa + 8;
#pragma unroll
        for (int nt = 0; nt < 4; nt++) {
            const int ocl = nw * 32 + nt * 8 + 2 * (lane & 3);
            const float b0 = sBias[ocl], b1 = sBias[ocl + 1];
            const float w0 = sWm[ocl],   w1 = sWm[ocl + 1];
            float v00 = fmaxf(acc[mt][nt][0] + b0, 0.f);
            float v01 = fmaxf(acc[mt][nt][1] + b1, 0.f);
            float v10 = fmaxf(acc[mt][nt][2] + b0, 0.f);
            float v11 = fmaxf(acc[mt][nt][3] + b1, 0.f);
            if (outp) {
                outp[(size_t)(ocb + ocl)     * NPIX + pxa] = v00;
                outp[(size_t)(ocb + ocl + 1) * NPIX + pxa] = v01;
                outp[(size_t)(ocb + ocl)     * NPIX + pxb] = v10;
                outp[(size_t)(ocb + ocl + 1) * NPIX + pxb] = v11;
            }
            lp[mt][0] = fmaf(w0, v00, fmaf(w1, v01, lp[mt][0]));
            lp[mt][1] = fmaf(w0, v10, fmaf(w1, v11, lp[mt][1]));
        }
    }
    // reduce over the 4 lanes of each quad (cols), then across N-warps via smem
#pragma unroll
    for (int mt = 0; mt < 4; mt++)
#pragma unroll
        for (int r = 0; r < 2; r++) {
            float v = lp[mt][r];
            v += __shfl_xor_sync(0xffffffffu, v, 1);
            v += __shfl_xor_sync(0xffffffffu, v, 2);
            lp[mt][r] = v;
        }
    if ((lane & 3) == 0) {
#pragma unroll
        for (int mt = 0; mt < 4; mt++) {
            const int pxl = mw * 64 + mt * 16 + (lane >> 2);
            sRed[nw * 128 + pxl]     = lp[mt][0];
            sRed[nw * 128 + pxl + 8] = lp[mt][1];
        }
    }
    __syncthreads();
    if (t < 128) {
        float s = sRed[t] + sRed[128 + t] + sRed[256 + t] + sRed[384 + t];
        logit[(size_t)blockIdx.y * NPIX + px0 + t] = s;
    }
}

// ---------------------------------------------------------------------------
// 5) mask = sigmoid(bm + sum of 4 logit partials)
// ---------------------------------------------------------------------------
__global__ void mask_kernel(const float* __restrict__ bm) {
    int p = blockIdx.x * blockDim.x + threadIdx.x;
    if (p >= NPIX) return;
    float s = bm[0] + g_logitM[p] + g_logitM[NPIX + p] + g_logitA[p] + g_logitA[NPIX + p];
    g_mask[p] = 1.0f / (1.0f + expf(-s));
}

// ---------------------------------------------------------------------------
// 6) out = m + mask * Maux
// ---------------------------------------------------------------------------
__global__ void final_kernel(const float* __restrict__ m, float* __restrict__ out) {
    int i4 = blockIdx.x * blockDim.x + threadIdx.x;
    if (i4 >= (CC * NPIX) / 4) return;
    int idx = i4 * 4;
    int p   = idx & (NPIX - 1);
    const float4 mv = ((const float4*)m)[i4];
    const float4 av = ((const float4*)g_Maux)[i4];
    const float4 kv = *(const float4*)&g_mask[p];
    float4 o;
    o.x = fmaf(kv.x, av.x, mv.x);
    o.y = fmaf(kv.y, av.y, mv.y);
    o.z = fmaf(kv.z, av.z, mv.z);
    o.w = fmaf(kv.w, av.w, mv.w);
    ((float4*)out)[i4] = o;
}

// ---------------------------------------------------------------------------
// launch
// ---------------------------------------------------------------------------
extern "C" void kernel_launch(void* const* d_in, const int* in_sizes, int n_in,
                              void* d_out, int out_size) {
    const float* m  = (const float*)d_in[0];
    const float* fb = (const float*)d_in[1];
    const float* fu = (const float*)d_in[2];
    const float* fd = (const float*)d_in[3];
    const float* Wf = (const float*)d_in[4];
    const float* bf = (const float*)d_in[5];
    const float* Wm = (const float*)d_in[6];
    const float* bm = (const float*)d_in[7];
    float* out = (float*)d_out;

    float* gAux  = nullptr; cudaGetSymbolAddress((void**)&gAux,  g_aux);
    float* gMaux = nullptr; cudaGetSymbolAddress((void**)&gMaux, g_Maux);
    float* gLM   = nullptr; cudaGetSymbolAddress((void**)&gLM,   g_logitM);
    float* gLA   = nullptr; cudaGetSymbolAddress((void**)&gLA,   g_logitA);

    cudaFuncSetAttribute(conv_mma, cudaFuncAttributeMaxDynamicSharedMemorySize, SMEM_SZ);

    geo_kernel<<<(NPIX + 255) / 256, 256>>>();
    wtb_kernel<<<(2 * 72 * 2048 + 255) / 256, 256>>>(Wf);
    aux_kernel<<<(CC * NPIX + 255) / 256, 256>>>(fb, fd, fu);

    dim3 cgrid(NPIX / 128, 2);
    conv_mma<<<cgrid, 256, SMEM_SZ>>>(m,    bf, Wm,       nullptr, gLM);
    conv_mma<<<cgrid, 256, SMEM_SZ>>>(gAux, bf, Wm + CC,  gMaux,   gLA);

    mask_kernel<<<(NPIX + 255) / 256, 256>>>(bm);
    final_kernel<<<((CC * NPIX) / 4 + 255) / 256, 256>>>(m, out);
}